// round 7
// baseline (speedup 1.0000x reference)
#include <cuda_runtime.h>

#define NUM_NET 2
#define V 100000
#define D 128
#define B 4096
#define K 5
#define NS 10

#define NTHREADS 256
#define WPB 8
#define NEIGH_WARPS (NUM_NET * B * 4)   // 32768: 4 warps per (i,b) on neigh tables
#define NODE_WARPS  (NUM_NET * B)       // 8192:  1 warp per (i,b) on node tables
#define TOT_WARPS (NEIGH_WARPS + NODE_WARPS)
#define NBLOCKS (TOT_WARPS / WPB)       // 5120

__device__ float g_part[NBLOCKS];
__device__ int   g_count = 0;

__device__ __forceinline__ float logsig_fast(float x) {
    // log(sigmoid(x)) = min(x,0) - log(1 + exp(-|x|)); fast-math (err ~1e-6 vs 1e-3 budget)
    return fminf(x, 0.0f) - __logf(1.0f + __expf(-fabsf(x)));
}

__device__ __forceinline__ float dot4(float4 a, float4 b) {
    return fmaf(a.x, b.x, fmaf(a.y, b.y, fmaf(a.z, b.z, a.w * b.w)));
}

__device__ __forceinline__ float dot_row(const float* __restrict__ tab, int id,
                                         float4 ne, int lane) {
    float4 c = __ldg(reinterpret_cast<const float4*>(tab + (size_t)id * D) + lane);
    return dot4(ne, c);
}

// Transpose-reduce 4 rows across the warp: returns, in each lane, the full
// 32-lane sum of row bitrev2(lane&3) (8 replicated copies across lane>>2).
// Cost: 6 SHFL total for 4 rows (vs 20 with per-row butterflies).
__device__ __forceinline__ float red4(float s0, float s1, float s2, float s3, int lane) {
    const bool hi0 = lane & 1;
    float d0 = hi0 ? s0 : s2;   // half to give away
    float d1 = hi0 ? s1 : s3;
    float r0 = __shfl_xor_sync(0xffffffffu, d0, 1);
    float r1 = __shfl_xor_sync(0xffffffffu, d1, 1);
    float a0 = (hi0 ? s2 : s0) + r0;   // rows {0 or 2}
    float a1 = (hi0 ? s3 : s1) + r1;   // rows {1 or 3}
    const bool hi1 = lane & 2;
    float d = hi1 ? a0 : a1;
    float r = __shfl_xor_sync(0xffffffffu, d, 2);
    float v = (hi1 ? a1 : a0) + r;
    v += __shfl_xor_sync(0xffffffffu, v, 4);
    v += __shfl_xor_sync(0xffffffffu, v, 8);
    v += __shfl_xor_sync(0xffffffffu, v, 16);
    return v;
}

// General 4-row batch: per-row table/index, per-row sign via negmask (bit rr),
// zero-weight dummies via zmask. Accumulates into the per-lane accumulator.
__device__ __forceinline__ void batch4(const float* t0, int i0, const float* t1, int i1,
                                       const float* t2, int i2, const float* t3, int i3,
                                       float4 ne, int lane, int rr,
                                       unsigned negmask, unsigned zmask,
                                       float wpos, float wneg, float& accL) {
    float s0 = dot_row(t0, i0, ne, lane);
    float s1 = dot_row(t1, i1, ne, lane);
    float s2 = dot_row(t2, i2, ne, lane);
    float s3 = dot_row(t3, i3, ne, lane);
    float v = red4(s0, s1, s2, s3, lane);
    bool neg = (negmask >> rr) & 1u;
    float x = neg ? -v : v;
    float w = neg ? wneg : wpos;
    if ((zmask >> rr) & 1u) w = 0.0f;
    accL = fmaf(w, logsig_fast(x), accL);
}

// Run of nbat pure-negative 4-row batches from one index array, one table.
__device__ __forceinline__ void neg_run4(const float* __restrict__ tab,
                                         const int* __restrict__ idx, int nbat,
                                         float4 ne, int lane, float wn, float& accL) {
    for (int m = 0; m < nbat; m++) {
        int i0 = __ldg(idx + 4 * m + 0);
        int i1 = __ldg(idx + 4 * m + 1);
        int i2 = __ldg(idx + 4 * m + 2);
        int i3 = __ldg(idx + 4 * m + 3);
        float v = red4(dot_row(tab, i0, ne, lane), dot_row(tab, i1, ne, lane),
                       dot_row(tab, i2, ne, lane), dot_row(tab, i3, ne, lane), lane);
        accL = fmaf(wn, logsig_fast(-v), accL);
    }
}

// Single negative row, warp-uniform result.
__device__ __forceinline__ float row_neg_one(const float* __restrict__ tab, int id,
                                             float4 ne, int lane) {
    float s = dot_row(tab, id, ne, lane);
    #pragma unroll
    for (int off = 16; off; off >>= 1)
        s += __shfl_xor_sync(0xffffffffu, s, off);
    return logsig_fast(-s);
}

__global__ void __launch_bounds__(NTHREADS)
loss_kernel(const float* __restrict__ node_tables,
            const float* __restrict__ neigh_tables,
            const int* __restrict__ nodes_idx,
            const int* __restrict__ neigh_idx,
            const int* __restrict__ role_idx,
            const int* __restrict__ neg_main,
            const int* __restrict__ neg_node,
            const int* __restrict__ neg_cross,
            const int* __restrict__ neg_role,
            float* __restrict__ out) {
    const int lane = threadIdx.x & 31;
    const int wid  = threadIdx.x >> 5;
    const int gw   = blockIdx.x * WPB + wid;
    const int rr   = ((lane & 1) << 1) | ((lane >> 1) & 1);   // logical row held by this lane
    const size_t VD = (size_t)V * D;

    const float CBW = 1.0f / (10.0f * (float)B);
    const float WH  = 0.1f;

    float accL = 0.0f;   // per-lane (rows replicated x8 across warp)
    float accW = 0.0f;   // warp-uniform

    if (gw < NEIGH_WARPS) {
        // ---- phase 1: neigh-table lists (t1 on gt_i, t3 on gt_j) ----
        const int pairid = gw >> 2;
        const int sub    = gw & 3;
        const int i = pairid / B;
        const int b = pairid % B;
        const int j = 1 - i;

        const float* gt;
        const int* negi;
        float wp, wn;
        if (sub < 2) {   // list A: main SGNS (gt_i, neg_main, w = 1)
            gt   = neigh_tables + (size_t)i * VD;
            negi = neg_main + (size_t)(i * B + b) * (K * NS);
            wp = -CBW / (float)K; wn = -CBW;
        } else {         // list B: cross neighbor (gt_j, neg_cross, w = HYP2)
            gt   = neigh_tables + (size_t)j * VD;
            negi = neg_cross + (size_t)((i * NUM_NET + j) * B + b) * (K * NS);
            wp = -WH * CBW / (float)K; wn = -WH * CBW;
        }
        const int* pos = neigh_idx + (i * B + b) * K;

        const int nid = __ldg(nodes_idx + i * B + b);
        const float4 ne = __ldg(reinterpret_cast<const float4*>(
            node_tables + (size_t)i * VD + (size_t)nid * D) + lane);

        if ((sub & 1) == 0) {
            // pos[0:4] | [pos4, n0, n1, n2] | n[3:23)   -> 28 rows
            batch4(gt, __ldg(pos + 0), gt, __ldg(pos + 1), gt, __ldg(pos + 2), gt, __ldg(pos + 3),
                   ne, lane, rr, 0x0u, 0x0u, wp, wn, accL);
            batch4(gt, __ldg(pos + 4), gt, __ldg(negi + 0), gt, __ldg(negi + 1), gt, __ldg(negi + 2),
                   ne, lane, rr, 0xEu, 0x0u, wp, wn, accL);
            neg_run4(gt, negi + 3, 5, ne, lane, wn, accL);
        } else {
            // n[23:47) | [n47, n48, n49, dummy]          -> 28 rows (1 dummy)
            neg_run4(gt, negi + 23, 6, ne, lane, wn, accL);
            batch4(gt, __ldg(negi + 47), gt, __ldg(negi + 48), gt, __ldg(negi + 49), gt, __ldg(negi + 49),
                   ne, lane, rr, 0xFu, 0x8u, wp, wn, accL);
        }
    } else {
        // ---- phase 2: node-table lists (t2 + both role terms), runs last ----
        const int pairid = gw - NEIGH_WARPS;
        const int i = pairid / B;
        const int b = pairid % B;
        const int j = 1 - i;

        const float* ntj = node_tables + (size_t)j * VD;
        const float* nt0 = node_tables;
        const float* nt1 = node_tables + VD;

        const int nid = __ldg(nodes_idx + i * B + b);
        const float4 ne = __ldg(reinterpret_cast<const float4*>(
            node_tables + (size_t)i * VD + (size_t)nid * D) + lane);

        const float w = -WH * CBW;
        const int* nn  = neg_node + (size_t)((i * NUM_NET + j) * B + b) * NS;
        const int* nr0 = neg_role + (size_t)((i * NUM_NET + 0) * B + b) * NS;
        const int* nr1 = neg_role + (size_t)((i * NUM_NET + 1) * B + b) * NS;
        const int r0p = __ldg(role_idx + (i * NUM_NET + 0) * B + b);
        const int r1p = __ldg(role_idx + (i * NUM_NET + 1) * B + b);

        // [t2pos, nn0, nn1, nn2]
        batch4(ntj, nid, ntj, __ldg(nn + 0), ntj, __ldg(nn + 1), ntj, __ldg(nn + 2),
               ne, lane, rr, 0xEu, 0x0u, w, w, accL);
        // nn[3:7)
        neg_run4(ntj, nn + 3, 1, ne, lane, w, accL);
        // [nn7, nn8, nn9, role0 pos]
        batch4(ntj, __ldg(nn + 7), ntj, __ldg(nn + 8), ntj, __ldg(nn + 9), nt0, r0p,
               ne, lane, rr, 0x7u, 0x0u, w, w, accL);
        // nr0[0:8)
        neg_run4(nt0, nr0, 2, ne, lane, w, accL);
        // [nr0_8, nr0_9, role1 pos, nr1_0]
        batch4(nt0, __ldg(nr0 + 8), nt0, __ldg(nr0 + 9), nt1, r1p, nt1, __ldg(nr1 + 0),
               ne, lane, rr, 0xBu, 0x0u, w, w, accL);
        // nr1[1:9)
        neg_run4(nt1, nr1 + 1, 2, ne, lane, w, accL);
        // single tail row nr1_9
        accW += w * row_neg_one(nt1, __ldg(nr1 + 9), ne, lane);
    }

    // fold the 8x row replication, reduce lanes
    float t = accL;
    #pragma unroll
    for (int off = 16; off; off >>= 1)
        t += __shfl_xor_sync(0xffffffffu, t, off);
    const float warp_total = t * 0.125f + accW;

    __shared__ float sacc[WPB];
    __shared__ int s_last;
    if (lane == 0) sacc[wid] = warp_total;
    __syncthreads();
    if (threadIdx.x == 0) {
        float bt = 0.0f;
        #pragma unroll
        for (int wds = 0; wds < WPB; wds++) bt += sacc[wds];
        g_part[blockIdx.x] = bt;      // always written: no zero-init needed
        __threadfence();
        int c = atomicAdd(&g_count, 1);
        s_last = (c == NBLOCKS - 1);
    }
    __syncthreads();

    // last block reduces all partials; fixed read order -> deterministic
    if (s_last) {
        __threadfence();
        __shared__ double sh[WPB];
        double td = 0.0;
        for (int k2 = threadIdx.x; k2 < NBLOCKS; k2 += NTHREADS)
            td += (double)g_part[k2];
        #pragma unroll
        for (int off = 16; off; off >>= 1)
            td += __shfl_xor_sync(0xffffffffu, td, off);
        if (lane == 0) sh[wid] = td;
        __syncthreads();
        if (threadIdx.x == 0) {
            double v = 0.0;
            #pragma unroll
            for (int wds = 0; wds < WPB; wds++) v += sh[wds];
            out[0] = (float)v;
            g_count = 0;              // reset for next graph replay
        }
    }
}

extern "C" void kernel_launch(void* const* d_in, const int* in_sizes, int n_in,
                              void* d_out, int out_size) {
    const float* node_tables  = (const float*)d_in[0];
    const float* neigh_tables = (const float*)d_in[1];
    const int*   nodes_idx    = (const int*)d_in[2];
    const int*   neigh_idx    = (const int*)d_in[3];
    const int*   role_idx     = (const int*)d_in[4];
    const int*   neg_main     = (const int*)d_in[5];
    const int*   neg_node     = (const int*)d_in[6];
    const int*   neg_cross    = (const int*)d_in[7];
    const int*   neg_role     = (const int*)d_in[8];

    (void)in_sizes; (void)n_in; (void)out_size;

    loss_kernel<<<NBLOCKS, NTHREADS>>>(node_tables, neigh_tables, nodes_idx,
                                       neigh_idx, role_idx, neg_main,
                                       neg_node, neg_cross, neg_role,
                                       (float*)d_out);
}